// round 15
// baseline (speedup 1.0000x reference)
#include <cuda_runtime.h>
#include <cuda_bf16.h>
#include <math.h>

#define NA 8400
#define BSZ 32
#define NM 32
#define NC 80
#define TOPK 9
#define AG 64
#define CAPB 320
#define NCELL 525            // 400 + 100 + 25
#define FINF 3.402823e38f

__device__ unsigned int g_maskpos[BSZ * NA];   // zero-init; k_assign restores
__device__ float2 g_sc[NA];                    // cell-sorted anchor centers
__device__ int    g_sidx[NA];                  // original anchor index
__device__ int    g_cellstart[NCELL + 1];

__device__ __forceinline__ int cell_of(int lvl, float x, float y) {
    const int   ncx = (lvl == 0) ? 20 : (lvl == 1) ? 10 : 5;
    const float inv = (lvl == 0) ? (1.0f/32.0f) : (lvl == 1) ? (1.0f/64.0f) : (1.0f/128.0f);
    int cx = (int)(x * inv); cx = cx < 0 ? 0 : (cx >= ncx ? ncx - 1 : cx);
    int cy = (int)(y * inv); cy = cy < 0 ? 0 : (cy >= ncx ? ncx - 1 : cy);
    const int base = (lvl == 0) ? 0 : (lvl == 1) ? 400 : 500;
    return base + cy * ncx + cx;
}

// Single-block CSR build: histogram -> prefix -> scatter.
__global__ __launch_bounds__(1024) void k_build(const float* __restrict__ anc)
{
    __shared__ int s_cnt[NCELL];
    __shared__ int s_start[NCELL + 1];
    const int tid = threadIdx.x;

    for (int c = tid; c < NCELL; c += 1024) s_cnt[c] = 0;
    __syncthreads();

    for (int i = tid; i < NA; i += 1024) {
        const float4 ab = ((const float4*)anc)[i];
        const float x = (ab.x + ab.z) * 0.5f;
        const float y = (ab.y + ab.w) * 0.5f;
        const int lvl = (i < 6400) ? 0 : (i < 8000) ? 1 : 2;
        atomicAdd(&s_cnt[cell_of(lvl, x, y)], 1);
    }
    __syncthreads();

    if (tid == 0) {
        int acc = 0;
        for (int c = 0; c < NCELL; ++c) { s_start[c] = acc; acc += s_cnt[c]; }
        s_start[NCELL] = acc;
    }
    __syncthreads();

    for (int c = tid; c < NCELL + 1; c += 1024) g_cellstart[c] = s_start[c];
    for (int c = tid; c < NCELL; c += 1024) s_cnt[c] = s_start[c];   // cursors
    __syncthreads();

    for (int i = tid; i < NA; i += 1024) {
        const float4 ab = ((const float4*)anc)[i];
        const float x = (ab.x + ab.z) * 0.5f;
        const float y = (ab.y + ab.w) * 0.5f;
        const int lvl = (i < 6400) ? 0 : (i < 8000) ? 1 : 2;
        const int pos = atomicAdd(&s_cnt[cell_of(lvl, x, y)], 1);
        g_sc[pos] = make_float2(x, y);
        g_sidx[pos] = i;
    }
}

// Warp-collective scan of one cell: push keys (filtered once top-9 known).
__device__ __forceinline__ void scan_cell(
    int cid, int lane, float gx, float gy,
    bool have9, unsigned long long k9max, int& cnt,
    unsigned long long* buf)
{
    const int s = g_cellstart[cid];
    const int e = g_cellstart[cid + 1];
    for (int ib = s; ib < e; ib += 32) {
        const int i = ib + lane;
        bool q = false;
        unsigned long long key = 0;
        if (i < e) {
            const float2 c = g_sc[i];
            const float dx = gx - c.x, dy = gy - c.y;
            const float d2 = fmaf(dx, dx, dy * dy);
            key = ((unsigned long long)__float_as_uint(d2) << 32) |
                  (unsigned int)g_sidx[i];
            q = (!have9) || (key < k9max);
        }
        const unsigned msk = __ballot_sync(0xffffffffu, q);
        if (q) {
            const int pos = cnt + __popc(msk & ((1u << lane) - 1u));
            if (pos < CAPB) buf[pos] = key;
        }
        cnt += __popc(msk);
    }
}

// One WARP per (b,g) pair: ring search per level, exact top-9, then tail.
__global__ __launch_bounds__(128) void k_pairs(
    const float* __restrict__ anc,
    const float* __restrict__ gtb,
    const float* __restrict__ mask_gt)
{
    __shared__ unsigned long long s_buf[4][CAPB];
    __shared__ unsigned long long s_top9[4][3][TOPK];

    const int tid  = threadIdx.x;
    const int lane = tid & 31;
    const int w    = tid >> 5;

    const int p = blockIdx.x * 4 + w;
    const int b = p >> 5;
    const int g = p & 31;
    if (mask_gt[p] <= 0.0f) return;             // warp-level; no block barriers

    const float4 gt = ((const float4*)gtb)[p];
    const float gx = (gt.x + gt.z) * 0.5f;
    const float gy = (gt.y + gt.w) * 0.5f;

    unsigned long long* buf = s_buf[w];

    #pragma unroll
    for (int lvl = 0; lvl < 3; ++lvl) {
        const int   ncx  = (lvl == 0) ? 20 : (lvl == 1) ? 10 : 5;
        const float cs   = (lvl == 0) ? 32.0f : (lvl == 1) ? 64.0f : 128.0f;
        const float inv  = 1.0f / cs;
        const int   base = (lvl == 0) ? 0 : (lvl == 1) ? 400 : 500;
        unsigned long long* top9 = s_top9[w][lvl];

        int gxc = (int)(gx * inv); gxc = gxc < 0 ? 0 : (gxc >= ncx ? ncx - 1 : gxc);
        int gyc = (int)(gy * inv); gyc = gyc < 0 ? 0 : (gyc >= ncx ? ncx - 1 : gyc);

        int cnt = 0;
        bool have9 = false;
        unsigned long long k9max = 0xFFFFFFFFFFFFFFFFull;

        for (int k = 0; k < ncx; ++k) {
            // ---- scan ring k ----
            if (k == 0) {
                scan_cell(base + gyc * ncx + gxc, lane, gx, gy, have9, k9max, cnt, buf);
            } else {
                for (int dx = -k; dx <= k; ++dx) {
                    const int cx = gxc + dx;
                    if (cx < 0 || cx >= ncx) continue;
                    const int cyt = gyc - k, cyb = gyc + k;
                    if (cyt >= 0)  scan_cell(base + cyt * ncx + cx, lane, gx, gy, have9, k9max, cnt, buf);
                    if (cyb < ncx) scan_cell(base + cyb * ncx + cx, lane, gx, gy, have9, k9max, cnt, buf);
                }
                for (int dy = -k + 1; dy <= k - 1; ++dy) {
                    const int cy = gyc + dy;
                    if (cy < 0 || cy >= ncx) continue;
                    const int cxl = gxc - k, cxr = gxc + k;
                    if (cxl >= 0)  scan_cell(base + cy * ncx + cxl, lane, gx, gy, have9, k9max, cnt, buf);
                    if (cxr < ncx) scan_cell(base + cy * ncx + cxr, lane, gx, gy, have9, k9max, cnt, buf);
                }
            }
            __syncwarp();

            // ---- merge: keep exact top-9 of buffer ----
            if (cnt >= TOPK) {
                const int C = cnt < CAPB ? cnt : CAPB;
                for (int i = lane; i < C; i += 32) {
                    const unsigned long long my = buf[i];
                    int r = 0;
                    for (int j = 0; j < C; ++j) r += (buf[j] < my) ? 1 : 0;
                    if (r < TOPK) top9[r] = my;
                }
                __syncwarp();
                if (lane < TOPK) buf[lane] = top9[lane];
                __syncwarp();
                cnt = TOPK;
                have9 = true;
                k9max = top9[TOPK - 1];
                const float d9 = __uint_as_float((unsigned)(k9max >> 32));
                const float bd = (float)k * cs;
                if (d9 < bd * bd) break;   // unscanned cells strictly farther
            }
            __syncwarp();
        }
    }
    __syncwarp();

    // ---- tail: candidate IoUs, mean+std(ddof=1) threshold, atomicOr ----
    float ov = 0.0f;
    int ca = 0;
    float4 ab = make_float4(0.f, 0.f, 0.f, 0.f);
    if (lane < 27) {
        const int lvl = lane / TOPK;
        const int j   = lane - lvl * TOPK;
        ca = (int)(unsigned int)s_top9[w][lvl][j];
        ab = ((const float4*)anc)[ca];
        const float area1 = (gt.z - gt.x) * (gt.w - gt.y);
        const float area2 = (ab.z - ab.x) * (ab.w - ab.y);
        const float ltx = fmaxf(gt.x, ab.x), lty = fmaxf(gt.y, ab.y);
        const float rbx = fminf(gt.z, ab.z), rby = fminf(gt.w, ab.w);
        const float ww = fmaxf(rbx - ltx, 0.0f), hh = fmaxf(rby - lty, 0.0f);
        const float o = ww * hh;
        ov = o / fmaxf(area1 + area2 - o, 1e-6f);
    }

    float s = (lane < 27) ? ov : 0.0f;
    #pragma unroll
    for (int sft = 16; sft > 0; sft >>= 1) s += __shfl_xor_sync(0xffffffffu, s, sft);
    const float mean = s * (1.0f / 27.0f);
    float dv = (lane < 27) ? (ov - mean) * (ov - mean) : 0.0f;
    #pragma unroll
    for (int sft = 16; sft > 0; sft >>= 1) dv += __shfl_xor_sync(0xffffffffu, dv, sft);
    const float thr = mean + sqrtf(dv * (1.0f / 26.0f));

    if (lane < 27 && ov > thr) {
        const float ax = (ab.x + ab.z) * 0.5f;
        const float ay = (ab.y + ab.w) * 0.5f;
        const float mn2 = fminf(fminf(ax - gt.x, ay - gt.y),
                                fminf(gt.z - ax, gt.w - ay));
        if (mn2 > 1e-9f) atomicOr(&g_maskpos[b * NA + ca], 1u << g);
    }
}

// One block per AG=64 anchors (R14-proven) + g_maskpos self-clear.
__global__ __launch_bounds__(256) void k_assign(
    const float* __restrict__ anc,
    const int*   __restrict__ gt_labels,
    const float* __restrict__ gtb,
    const float* __restrict__ pd,
    float* __restrict__ o_lab,
    float* __restrict__ o_box,
    float* __restrict__ o_scr,
    float* __restrict__ o_fg)
{
    __shared__ int   s_lab[AG];
    __shared__ float s_scr[AG];

    const int base = blockIdx.x * AG;
    const int tid  = threadIdx.x;

    if (tid < AG) {
        const int idx = base + tid;
        const int b = idx / NA;
        const int a = idx - b * NA;

        const unsigned int m = g_maskpos[idx];
        g_maskpos[idx] = 0u;                 // restore invariant for next call
        const int cnt = __popc(m);
        int tgt = 0;
        const bool fg = (cnt > 0);

        if (cnt == 1) {
            tgt = __ffs(m) - 1;
        } else if (cnt > 1) {
            const float4 ab = ((const float4*)anc)[a];
            const float area2 = (ab.z - ab.x) * (ab.w - ab.y);
            float best = -1.0f;
            for (int gg = 0; gg < NM; ++gg) {
                const float4 gb = ((const float4*)gtb)[b * NM + gg];
                const float area1 = (gb.z - gb.x) * (gb.w - gb.y);
                const float ltx = fmaxf(gb.x, ab.x), lty = fmaxf(gb.y, ab.y);
                const float rbx = fminf(gb.z, ab.z), rby = fminf(gb.w, ab.w);
                const float ww = fmaxf(rbx - ltx, 0.0f), hh = fmaxf(rby - lty, 0.0f);
                const float ovv = ww * hh;
                const float v = ovv / fmaxf(area1 + area2 - ovv, 1e-6f);
                if (v > best) { best = v; tgt = gg; }
            }
        }

        const int label = fg ? gt_labels[b * NM + tgt] : NC;
        const float4 tb = ((const float4*)gtb)[b * NM + tgt];

        o_lab[idx] = (float)label;
        ((float4*)o_box)[idx] = tb;
        o_fg[idx] = fg ? 1.0f : 0.0f;

        float score = 0.0f;
        if (fg) {
            const float4 pb = ((const float4*)pd)[(size_t)b * NA + a];
            const float iw = fmaxf(fminf(tb.z, pb.z) - fmaxf(tb.x, pb.x), 0.0f);
            const float ih = fmaxf(fminf(tb.w, pb.w) - fmaxf(tb.y, pb.y), 0.0f);
            const float ovv = iw * ih;
            const float a1 = fmaxf(tb.z - tb.x, 0.0f) * fmaxf(tb.w - tb.y, 0.0f);
            const float a2 = fmaxf(pb.z - pb.x, 0.0f) * fmaxf(pb.w - pb.y, 0.0f);
            score = ovv / (a1 + a2 - ovv + 1e-9f);
        }
        s_lab[tid] = fg ? label : -1;
        s_scr[tid] = score;
    }
    __syncthreads();

    float4* sc4 = (float4*)o_scr + (size_t)base * (NC / 4);
    #pragma unroll
    for (int it = 0; it < AG * (NC / 4) / 256; ++it) {
        const int j  = it * 256 + tid;
        const int an = j / (NC / 4);
        const int q  = j - an * (NC / 4);
        float4 v = make_float4(0.f, 0.f, 0.f, 0.f);
        const int l = s_lab[an];
        if (l >= 0 && (l >> 2) == q) {
            const float sc = s_scr[an];
            if ((l & 3) == 0) v.x = sc;
            else if ((l & 3) == 1) v.y = sc;
            else if ((l & 3) == 2) v.z = sc;
            else v.w = sc;
        }
        sc4[j] = v;
    }
}

extern "C" void kernel_launch(void* const* d_in, const int* in_sizes, int n_in,
                              void* d_out, int out_size)
{
    const float* anc = (const float*)d_in[0];   // [8400,4]
    const int*   gtl = (const int*)  d_in[1];   // [32,32,1]
    const float* gtb = (const float*)d_in[2];   // [32,32,4]
    const float* mgt = (const float*)d_in[3];   // [32,32,1]
    const float* pd  = (const float*)d_in[4];   // [32,8400,4]

    float* out   = (float*)d_out;
    float* o_lab = out;
    float* o_box = o_lab + (size_t)BSZ * NA;
    float* o_scr = o_box + (size_t)BSZ * NA * 4;
    float* o_fg  = o_scr + (size_t)BSZ * NA * NC;

    k_build<<<1, 1024>>>(anc);
    k_pairs<<<BSZ * NM / 4, 128>>>(anc, gtb, mgt);
    k_assign<<<BSZ * NA / AG, 256>>>(anc, gtl, gtb, pd,
                                     o_lab, o_box, o_scr, o_fg);
}

// round 17
// speedup vs baseline: 1.7520x; 1.7520x over previous
#include <cuda_runtime.h>
#include <cuda_bf16.h>
#include <math.h>

#define NA 8400
#define BSZ 32
#define NM 32
#define NC 80
#define TOPK 9
#define CAPW 64
#define AG 64
#define FINF 3.402823e38f

// Padded per-level center layout (each a multiple of 128):
#define P0   6400
#define P1   1664
#define P2   512
#define PO0  0
#define PO1  6400
#define PO2  8064
#define PTOT 8576

__device__ unsigned int g_maskpos[BSZ * NA];
__device__ float2       g_acp[PTOT];             // padded anchor centers
__device__ unsigned long long g_keys27[BSZ * NM * 27];

// Zero gt bitmask, fill padded centers (pads = far sentinel).
__global__ __launch_bounds__(256) void k_prep(const float* __restrict__ anc)
{
    const int i = blockIdx.x * blockDim.x + threadIdx.x;
    if (i < BSZ * NA / 4) ((uint4*)g_maskpos)[i] = make_uint4(0u, 0u, 0u, 0u);
    if (i < PTOT) {
        int realIdx = -1;
        if (i < PO1)      realIdx = i;
        else if (i < PO2) { const int li = i - PO1; if (li < 1600) realIdx = 6400 + li; }
        else              { const int li = i - PO2; if (li < 400)  realIdx = 8000 + li; }
        float2 c = make_float2(3.0e18f, 3.0e18f);
        if (realIdx >= 0) {
            const float4 ab = ((const float4*)anc)[realIdx];
            c = make_float2((ab.x + ab.z) * 0.5f, (ab.y + ab.w) * 0.5f);
        }
        g_acp[i] = c;
    }
}

// One BLOCK (128 thr = 4 warps) per (pair, level) — 1D grid, lvl fastest.
// R14-proven two-pass top-9 for a single level; 9 exact keys -> g_keys27.
__global__ __launch_bounds__(128) void k_topk(
    const float* __restrict__ gtb,
    const float* __restrict__ mask_gt)
{
    __shared__ unsigned long long s_keys[36];
    __shared__ unsigned long long s_buf[4][CAPW];
    __shared__ float s_min[4][32];
    __shared__ int   s_cnt[4];

    const int tid  = threadIdx.x;
    const int lane = tid & 31;
    const int wq   = tid >> 5;

    const int bid = blockIdx.x;
    const int p   = bid / 3;
    const int lvl = bid - p * 3;
    if (mask_gt[p] <= 0.0f) return;

    const float4 gt = ((const float4*)gtb)[p];
    const float gx = (gt.x + gt.z) * 0.5f;
    const float gy = (gt.y + gt.w) * 0.5f;

    const int Lp    = (lvl == 0) ? P0  : (lvl == 1) ? P1  : P2;
    const int ofs   = (lvl == 0) ? PO0 : (lvl == 1) ? PO1 : PO2;
    const int realS = (lvl == 0) ? 0   : (lvl == 1) ? 6400 : 8000;

    // ---- Pass 1: per-lane min of squared distance ----
    float mn = FINF;
    #pragma unroll 4
    for (int i = tid; i < Lp; i += 128) {
        const float2 c = g_acp[ofs + i];
        const float dx = gx - c.x, dy = gy - c.y;
        mn = fminf(mn, fmaf(dx, dx, dy * dy));
    }

    // ---- T = 9th smallest of this warp's 32 lane minima (rank-select) ----
    s_min[wq][lane] = mn;
    __syncwarp();
    int rank = 0;
    #pragma unroll
    for (int j = 0; j < 32; ++j) {
        const float o = s_min[wq][j];
        rank += (o < mn || (o == mn && j < lane)) ? 1 : 0;
    }
    const unsigned rm = __ballot_sync(0xffffffffu, rank == 8);
    const float T = __shfl_sync(0xffffffffu, mn, __ffs(rm) - 1);

    // ---- Pass 2: push keys with d2 <= T (pads never qualify) ----
    if (lane == 0) s_cnt[wq] = 0;
    __syncwarp();
    #pragma unroll 4
    for (int i = tid; i < Lp; i += 128) {
        const float2 c = g_acp[ofs + i];
        const float dx = gx - c.x, dy = gy - c.y;
        const float d2 = fmaf(dx, dx, dy * dy);
        if (d2 <= T) {
            const int pos = atomicAdd(&s_cnt[wq], 1);
            if (pos < CAPW)
                s_buf[wq][pos] =
                    ((unsigned long long)__float_as_uint(d2) << 32) |
                    (unsigned int)(realS + i);
        }
    }
    __syncwarp();

    // ---- Per-warp rank-select top-9 of C buffered keys ----
    int C = s_cnt[wq]; if (C > CAPW) C = CAPW;      // C >= 9 guaranteed
    for (int i = lane; i < C; i += 32) {
        const unsigned long long my = s_buf[wq][i];
        int r = 0;
        for (int j = 0; j < C; ++j)
            r += (s_buf[wq][j] < my) ? 1 : 0;
        if (r < TOPK)
            s_keys[wq * TOPK + r] = my;
    }
    __syncthreads();

    // ---- Warp 0: rank-select top-9 of the 36 keys -> global ----
    if (wq == 0) {
        #pragma unroll
        for (int half = 0; half < 2; ++half) {
            const int i = lane + half * 32;
            if (i < 36) {
                const unsigned long long my = s_keys[i];
                int r = 0;
                #pragma unroll
                for (int j = 0; j < 36; ++j)
                    r += (s_keys[j] < my) ? 1 : 0;
                if (r < TOPK)
                    g_keys27[p * 27 + lvl * TOPK + r] = my;
            }
        }
    }
}

// One WARP per pair: read 27 keys, IoU, mean+std threshold, atomicOr.
__global__ __launch_bounds__(128) void k_tail(
    const float* __restrict__ anc,
    const float* __restrict__ gtb,
    const float* __restrict__ mask_gt)
{
    const int tid  = threadIdx.x;
    const int lane = tid & 31;
    const int w    = tid >> 5;

    const int p = blockIdx.x * 4 + w;
    const int b = p >> 5;
    const int g = p & 31;
    if (mask_gt[p] <= 0.0f) return;

    const float4 gt = ((const float4*)gtb)[p];

    // Candidate overlaps (_iou2d: unclipped areas, union eps 1e-6)
    float ov = 0.0f;
    int ca = 0;
    float4 ab = make_float4(0.f, 0.f, 0.f, 0.f);
    if (lane < 27) {
        ca = (int)(unsigned int)g_keys27[p * 27 + lane];
        ab = ((const float4*)anc)[ca];
        const float area1 = (gt.z - gt.x) * (gt.w - gt.y);
        const float area2 = (ab.z - ab.x) * (ab.w - ab.y);
        const float ltx = fmaxf(gt.x, ab.x), lty = fmaxf(gt.y, ab.y);
        const float rbx = fminf(gt.z, ab.z), rby = fminf(gt.w, ab.w);
        const float ww = fmaxf(rbx - ltx, 0.0f), hh = fmaxf(rby - lty, 0.0f);
        const float o = ww * hh;
        ov = o / fmaxf(area1 + area2 - o, 1e-6f);
    }

    float s = (lane < 27) ? ov : 0.0f;
    #pragma unroll
    for (int sft = 16; sft > 0; sft >>= 1) s += __shfl_xor_sync(0xffffffffu, s, sft);
    const float mean = s * (1.0f / 27.0f);
    float dv = (lane < 27) ? (ov - mean) * (ov - mean) : 0.0f;
    #pragma unroll
    for (int sft = 16; sft > 0; sft >>= 1) dv += __shfl_xor_sync(0xffffffffu, dv, sft);
    const float thr = mean + sqrtf(dv * (1.0f / 26.0f));

    if (lane < 27 && ov > thr) {
        const float ax = (ab.x + ab.z) * 0.5f;
        const float ay = (ab.y + ab.w) * 0.5f;
        const float mn2 = fminf(fminf(ax - gt.x, ay - gt.y),
                                fminf(gt.z - ax, gt.w - ay));
        if (mn2 > 1e-9f) atomicOr(&g_maskpos[b * NA + ca], 1u << g);
    }
}

// One block per AG=64 anchors. (R14-proven version.)
__global__ __launch_bounds__(256) void k_assign(
    const float* __restrict__ anc,
    const int*   __restrict__ gt_labels,
    const float* __restrict__ gtb,
    const float* __restrict__ pd,
    float* __restrict__ o_lab,
    float* __restrict__ o_box,
    float* __restrict__ o_scr,
    float* __restrict__ o_fg)
{
    __shared__ int   s_lab[AG];
    __shared__ float s_scr[AG];

    const int base = blockIdx.x * AG;
    const int tid  = threadIdx.x;

    if (tid < AG) {
        const int idx = base + tid;
        const int b = idx / NA;
        const int a = idx - b * NA;

        const unsigned int m = g_maskpos[idx];
        const int cnt = __popc(m);
        int tgt = 0;
        const bool fg = (cnt > 0);

        if (cnt == 1) {
            tgt = __ffs(m) - 1;
        } else if (cnt > 1) {
            const float4 ab = ((const float4*)anc)[a];
            const float area2 = (ab.z - ab.x) * (ab.w - ab.y);
            float best = -1.0f;
            for (int gg = 0; gg < NM; ++gg) {
                const float4 gb = ((const float4*)gtb)[b * NM + gg];
                const float area1 = (gb.z - gb.x) * (gb.w - gb.y);
                const float ltx = fmaxf(gb.x, ab.x), lty = fmaxf(gb.y, ab.y);
                const float rbx = fminf(gb.z, ab.z), rby = fminf(gb.w, ab.w);
                const float ww = fmaxf(rbx - ltx, 0.0f), hh = fmaxf(rby - lty, 0.0f);
                const float ovv = ww * hh;
                const float v = ovv / fmaxf(area1 + area2 - ovv, 1e-6f);
                if (v > best) { best = v; tgt = gg; }
            }
        }

        const int label = fg ? gt_labels[b * NM + tgt] : NC;
        const float4 tb = ((const float4*)gtb)[b * NM + tgt];

        o_lab[idx] = (float)label;
        ((float4*)o_box)[idx] = tb;
        o_fg[idx] = fg ? 1.0f : 0.0f;

        float score = 0.0f;
        if (fg) {
            const float4 pb = ((const float4*)pd)[(size_t)b * NA + a];
            const float iw = fmaxf(fminf(tb.z, pb.z) - fmaxf(tb.x, pb.x), 0.0f);
            const float ih = fmaxf(fminf(tb.w, pb.w) - fmaxf(tb.y, pb.y), 0.0f);
            const float ovv = iw * ih;
            const float a1 = fmaxf(tb.z - tb.x, 0.0f) * fmaxf(tb.w - tb.y, 0.0f);
            const float a2 = fmaxf(pb.z - pb.x, 0.0f) * fmaxf(pb.w - pb.y, 0.0f);
            score = ovv / (a1 + a2 - ovv + 1e-9f);
        }
        s_lab[tid] = fg ? label : -1;
        s_scr[tid] = score;
    }
    __syncthreads();

    float4* sc4 = (float4*)o_scr + (size_t)base * (NC / 4);
    #pragma unroll
    for (int it = 0; it < AG * (NC / 4) / 256; ++it) {
        const int j  = it * 256 + tid;
        const int an = j / (NC / 4);
        const int q  = j - an * (NC / 4);
        float4 v = make_float4(0.f, 0.f, 0.f, 0.f);
        const int l = s_lab[an];
        if (l >= 0 && (l >> 2) == q) {
            const float sc = s_scr[an];
            if ((l & 3) == 0) v.x = sc;
            else if ((l & 3) == 1) v.y = sc;
            else if ((l & 3) == 2) v.z = sc;
            else v.w = sc;
        }
        sc4[j] = v;
    }
}

extern "C" void kernel_launch(void* const* d_in, const int* in_sizes, int n_in,
                              void* d_out, int out_size)
{
    const float* anc = (const float*)d_in[0];   // [8400,4]
    const int*   gtl = (const int*)  d_in[1];   // [32,32,1]
    const float* gtb = (const float*)d_in[2];   // [32,32,4]
    const float* mgt = (const float*)d_in[3];   // [32,32,1]
    const float* pd  = (const float*)d_in[4];   // [32,8400,4]

    float* out   = (float*)d_out;
    float* o_lab = out;
    float* o_box = o_lab + (size_t)BSZ * NA;
    float* o_scr = o_box + (size_t)BSZ * NA * 4;
    float* o_fg  = o_scr + (size_t)BSZ * NA * NC;

    k_prep<<<(BSZ * NA / 4 + 255) / 256, 256>>>(anc);
    k_topk<<<BSZ * NM * 3, 128>>>(gtb, mgt);
    k_tail<<<BSZ * NM / 4, 128>>>(anc, gtb, mgt);
    k_assign<<<BSZ * NA / AG, 256>>>(anc, gtl, gtb, pd,
                                     o_lab, o_box, o_scr, o_fg);
}